// round 7
// baseline (speedup 1.0000x reference)
#include <cuda_runtime.h>
#include <math.h>

#define BATCH   1024
#define EMBD    512
#define RNND    512
#define GATES   2048
#define VOCABO  11998
#define VPAD    12032      // 188 * 64
#define FEATSD  4096
#define TSTEPS  15

// ---------------- scratch (__device__ globals; no runtime allocation) ----------
__device__ float g_x[BATCH * EMBD];          // current LSTM input
__device__ float g_h[BATCH * RNND];
__device__ float g_c[BATCH * RNND];
__device__ float g_gates[BATCH * GATES];
__device__ float g_logits[BATCH * VPAD];     // 49.3 MB scratch, pad cols unused
__device__ int   g_words[BATCH];

// ---------------- activations (expf-only; robust under fast-math) --------------
__device__ __forceinline__ float sigm_f(float x) {
    return 1.0f / (1.0f + expf(-x));
}
__device__ __forceinline__ float tanh_f(float x) {
    float e = expf(-2.0f * fabsf(x));
    float t = (1.0f - e) / (1.0f + e);
    return copysignf(t, x);
}

// ================================================================================
// Uniform simple GEMM tile scheme used by all three GEMMs:
//   C[64 x 64] tile of A[M,K] @ B[N,K]^T, BK = 32, 256 threads, 4x4 per thread.
// ================================================================================

// -------- Kernel 1: g_x = relu(img[1024,4096] @ W_feats^T) + zero h, c ----------
__global__ __launch_bounds__(256) void k_prime(const float* __restrict__ A,
                                               const float* __restrict__ Bw,
                                               const float* __restrict__ bias) {
    __shared__ float As[32][68];
    __shared__ float Bs[32][68];
    const int tid = threadIdx.x;
    const int bm = blockIdx.y * 64;       // batch rows   (grid.y = 16)
    const int bn = blockIdx.x * 64;       // output cols  (grid.x = 8)
    const int lr = tid >> 3;              // 0..31
    const int lk = (tid & 7) << 2;        // 0,4,...,28
    const int m0 = (tid >> 4) << 2;       // 0..60
    const int n0 = (tid & 15) << 2;       // 0..60
    float acc[4][4] = {};

    for (int s = 0; s < FEATSD / 32; s++) {
        const int ka = s * 32 + lk;
        float4 a0 = *(const float4*)&A [(size_t)(bm + lr)      * FEATSD + ka];
        float4 a1 = *(const float4*)&A [(size_t)(bm + lr + 32) * FEATSD + ka];
        float4 b0 = *(const float4*)&Bw[(size_t)(bn + lr)      * FEATSD + ka];
        float4 b1 = *(const float4*)&Bw[(size_t)(bn + lr + 32) * FEATSD + ka];
        __syncthreads();
        As[lk+0][lr] = a0.x; As[lk+1][lr] = a0.y; As[lk+2][lr] = a0.z; As[lk+3][lr] = a0.w;
        As[lk+0][lr+32] = a1.x; As[lk+1][lr+32] = a1.y; As[lk+2][lr+32] = a1.z; As[lk+3][lr+32] = a1.w;
        Bs[lk+0][lr] = b0.x; Bs[lk+1][lr] = b0.y; Bs[lk+2][lr] = b0.z; Bs[lk+3][lr] = b0.w;
        Bs[lk+0][lr+32] = b1.x; Bs[lk+1][lr+32] = b1.y; Bs[lk+2][lr+32] = b1.z; Bs[lk+3][lr+32] = b1.w;
        __syncthreads();
        #pragma unroll
        for (int kk = 0; kk < 32; kk++) {
            float4 a = *(const float4*)&As[kk][m0];
            float4 b = *(const float4*)&Bs[kk][n0];
            acc[0][0] += a.x*b.x; acc[0][1] += a.x*b.y; acc[0][2] += a.x*b.z; acc[0][3] += a.x*b.w;
            acc[1][0] += a.y*b.x; acc[1][1] += a.y*b.y; acc[1][2] += a.y*b.z; acc[1][3] += a.y*b.w;
            acc[2][0] += a.z*b.x; acc[2][1] += a.z*b.y; acc[2][2] += a.z*b.z; acc[2][3] += a.z*b.w;
            acc[3][0] += a.w*b.x; acc[3][1] += a.w*b.y; acc[3][2] += a.w*b.z; acc[3][3] += a.w*b.w;
        }
    }

    #pragma unroll
    for (int i = 0; i < 4; i++) {
        int m = bm + m0 + i;
        #pragma unroll
        for (int j = 0; j < 4; j++) {
            int n = bn + n0 + j;
            float v = fmaxf(acc[i][j] + bias[n], 0.0f);
            int idx = m * EMBD + n;
            g_x[idx] = v;
            g_h[idx] = 0.0f;
            g_c[idx] = 0.0f;
        }
    }
}

// -------- Kernel 2: g_gates = [g_x | g_h] @ [W_ih | W_hh]^T + b_ih + b_hh -------
__global__ __launch_bounds__(256) void k_gates(const float* __restrict__ Wih,
                                               const float* __restrict__ Whh,
                                               const float* __restrict__ bih,
                                               const float* __restrict__ bhh) {
    __shared__ float As[32][68];
    __shared__ float Bs[32][68];
    const int tid = threadIdx.x;
    const int bm = blockIdx.y * 64;       // batch (grid.y = 16)
    const int bn = blockIdx.x * 64;       // gate cols (grid.x = 32)
    const int lr = tid >> 3;
    const int lk = (tid & 7) << 2;
    const int m0 = (tid >> 4) << 2;
    const int n0 = (tid & 15) << 2;
    float acc[4][4] = {};

    for (int s = 0; s < 32; s++) {        // 32 slabs of 32 -> virtual K = 1024
        const int sk = s * 32;
        const float* Ap = (sk < 512) ? g_x : g_h;
        const float* Bp = (sk < 512) ? Wih : Whh;
        const int ka = (sk & 511) + lk;
        float4 a0 = *(const float4*)&Ap[(size_t)(bm + lr)      * 512 + ka];
        float4 a1 = *(const float4*)&Ap[(size_t)(bm + lr + 32) * 512 + ka];
        float4 b0 = *(const float4*)&Bp[(size_t)(bn + lr)      * 512 + ka];
        float4 b1 = *(const float4*)&Bp[(size_t)(bn + lr + 32) * 512 + ka];
        __syncthreads();
        As[lk+0][lr] = a0.x; As[lk+1][lr] = a0.y; As[lk+2][lr] = a0.z; As[lk+3][lr] = a0.w;
        As[lk+0][lr+32] = a1.x; As[lk+1][lr+32] = a1.y; As[lk+2][lr+32] = a1.z; As[lk+3][lr+32] = a1.w;
        Bs[lk+0][lr] = b0.x; Bs[lk+1][lr] = b0.y; Bs[lk+2][lr] = b0.z; Bs[lk+3][lr] = b0.w;
        Bs[lk+0][lr+32] = b1.x; Bs[lk+1][lr+32] = b1.y; Bs[lk+2][lr+32] = b1.z; Bs[lk+3][lr+32] = b1.w;
        __syncthreads();
        #pragma unroll
        for (int kk = 0; kk < 32; kk++) {
            float4 a = *(const float4*)&As[kk][m0];
            float4 b = *(const float4*)&Bs[kk][n0];
            acc[0][0] += a.x*b.x; acc[0][1] += a.x*b.y; acc[0][2] += a.x*b.z; acc[0][3] += a.x*b.w;
            acc[1][0] += a.y*b.x; acc[1][1] += a.y*b.y; acc[1][2] += a.y*b.z; acc[1][3] += a.y*b.w;
            acc[2][0] += a.z*b.x; acc[2][1] += a.z*b.y; acc[2][2] += a.z*b.z; acc[2][3] += a.z*b.w;
            acc[3][0] += a.w*b.x; acc[3][1] += a.w*b.y; acc[3][2] += a.w*b.z; acc[3][3] += a.w*b.w;
        }
    }

    #pragma unroll
    for (int i = 0; i < 4; i++) {
        int m = bm + m0 + i;
        #pragma unroll
        for (int j = 0; j < 4; j++) {
            int n = bn + n0 + j;
            g_gates[m * GATES + n] = acc[i][j] + bih[n] + bhh[n];
        }
    }
}

// -------- Kernel 3: g_logits = g_h @ W_out^T + b_out (materialized) -------------
__global__ __launch_bounds__(256) void k_logits(const float* __restrict__ Wout,
                                                const float* __restrict__ bout) {
    __shared__ float As[32][68];
    __shared__ float Bs[32][68];
    const int tid = threadIdx.x;
    const int bm = blockIdx.y * 64;       // batch (grid.y = 16)
    const int bn = blockIdx.x * 64;       // vocab cols (grid.x = 188)
    const int lr = tid >> 3;
    const int lk = (tid & 7) << 2;
    const int m0 = (tid >> 4) << 2;
    const int n0 = (tid & 15) << 2;
    float acc[4][4] = {};

    const int br0 = bn + lr, br1 = bn + lr + 32;
    const bool v0 = br0 < VOCABO, v1 = br1 < VOCABO;
    const float4 z4 = make_float4(0.f, 0.f, 0.f, 0.f);

    for (int s = 0; s < 16; s++) {        // K = 512
        const int ka = s * 32 + lk;
        float4 a0 = *(const float4*)&g_h[(size_t)(bm + lr)      * 512 + ka];
        float4 a1 = *(const float4*)&g_h[(size_t)(bm + lr + 32) * 512 + ka];
        float4 b0 = v0 ? *(const float4*)&Wout[(size_t)br0 * 512 + ka] : z4;
        float4 b1 = v1 ? *(const float4*)&Wout[(size_t)br1 * 512 + ka] : z4;
        __syncthreads();
        As[lk+0][lr] = a0.x; As[lk+1][lr] = a0.y; As[lk+2][lr] = a0.z; As[lk+3][lr] = a0.w;
        As[lk+0][lr+32] = a1.x; As[lk+1][lr+32] = a1.y; As[lk+2][lr+32] = a1.z; As[lk+3][lr+32] = a1.w;
        Bs[lk+0][lr] = b0.x; Bs[lk+1][lr] = b0.y; Bs[lk+2][lr] = b0.z; Bs[lk+3][lr] = b0.w;
        Bs[lk+0][lr+32] = b1.x; Bs[lk+1][lr+32] = b1.y; Bs[lk+2][lr+32] = b1.z; Bs[lk+3][lr+32] = b1.w;
        __syncthreads();
        #pragma unroll
        for (int kk = 0; kk < 32; kk++) {
            float4 a = *(const float4*)&As[kk][m0];
            float4 b = *(const float4*)&Bs[kk][n0];
            acc[0][0] += a.x*b.x; acc[0][1] += a.x*b.y; acc[0][2] += a.x*b.z; acc[0][3] += a.x*b.w;
            acc[1][0] += a.y*b.x; acc[1][1] += a.y*b.y; acc[1][2] += a.y*b.z; acc[1][3] += a.y*b.w;
            acc[2][0] += a.z*b.x; acc[2][1] += a.z*b.y; acc[2][2] += a.z*b.z; acc[2][3] += a.z*b.w;
            acc[3][0] += a.w*b.x; acc[3][1] += a.w*b.y; acc[3][2] += a.w*b.z; acc[3][3] += a.w*b.w;
        }
    }

    #pragma unroll
    for (int i = 0; i < 4; i++) {
        int m = bm + m0 + i;
        #pragma unroll
        for (int j = 0; j < 4; j++) {
            int n = bn + n0 + j;
            if (n < VOCABO)
                g_logits[m * VPAD + n] = acc[i][j] + bout[n];
        }
    }
}

// -------- Kernel 4: LSTM pointwise (i, f, g, o torch order) ---------------------
__global__ void k_point() {
    int idx = blockIdx.x * blockDim.x + threadIdx.x;   // 1024*512 threads
    int b = idx >> 9, n = idx & 511;
    const float* g = g_gates + b * GATES;
    float ig = sigm_f(g[n]);
    float fg = sigm_f(g[512 + n]);
    float gg = tanh_f(g[1024 + n]);
    float og = sigm_f(g[1536 + n]);
    float c = fg * g_c[idx] + ig * gg;
    g_c[idx] = c;
    g_h[idx] = og * tanh_f(c);
}

// -------- Kernel 5: embedding gather -------------------------------------------
__global__ void k_embed(const float* __restrict__ emb, int t) {
    int b = blockIdx.x;
    int w = (t == 0) ? 1 : g_words[b];                 // START token = 1
    const float4* src = (const float4*)(emb + (size_t)w * EMBD);
    float4* dst = (float4*)(g_x + (size_t)b * EMBD);
    dst[threadIdx.x] = src[threadIdx.x];               // 128 thr x float4 = 512
}

// -------- Kernel 6: per-row argmax; OUTPUT WRITTEN AS float32 -------------------
__global__ __launch_bounds__(256) void k_argmax(float* __restrict__ out, int t) {
    __shared__ float sv[256];
    __shared__ int   si[256];
    const int b = blockIdx.x;
    const int tid = threadIdx.x;
    const float* row = g_logits + (size_t)b * VPAD;

    float bv = -1e30f;
    int bi = 0;
    for (int n = tid; n < VOCABO; n += 256) {
        float v = row[n];
        if (v > bv) { bv = v; bi = n; }                // strict > keeps lowest idx
    }
    sv[tid] = bv; si[tid] = bi;
    __syncthreads();
    for (int s = 128; s > 0; s >>= 1) {
        if (tid < s) {
            float ov = sv[tid + s]; int oi = si[tid + s];
            if (ov > sv[tid] || (ov == sv[tid] && oi < si[tid])) {
                sv[tid] = ov; si[tid] = oi;
            }
        }
        __syncthreads();
    }
    if (tid == 0) {
        out[b * TSTEPS + t] = (float)si[0];            // <-- float32 output dtype
        g_words[b] = si[0] + 2;                        // next embedding row
    }
}

// ================================================================================
extern "C" void kernel_launch(void* const* d_in, const int* in_sizes, int n_in,
                              void* d_out, int out_size) {
    // ---- bind inputs BY ELEMENT COUNT (insertion order for equal-size pairs) ---
    const float *img = 0, *W_feats = 0, *b_feats = 0, *W_ih = 0, *W_hh = 0,
                *b_ih = 0, *b_hh = 0, *emb = 0, *W_out = 0, *b_out = 0;
    for (int i = 0; i < n_in; i++) {
        const float* p = (const float*)d_in[i];
        switch (in_sizes[i]) {
            case 4194304: img = p; break;
            case 2097152: W_feats = p; break;
            case 512:     b_feats = p; break;
            case 1048576: if (!W_ih) W_ih = p; else W_hh = p; break;  // insertion order
            case 2048:    if (!b_ih) b_ih = p; else b_hh = p; break;  // (symmetric)
            case 6144000: emb = p; break;
            case 6142976: W_out = p; break;
            case 11998:   b_out = p; break;
            default: break;
        }
    }
    if (!img || !W_feats || !b_feats || !W_ih || !W_hh || !b_ih || !b_hh ||
        !emb || !W_out || !b_out) {
        img     = (const float*)d_in[0];
        W_feats = (const float*)d_in[1];
        b_feats = (const float*)d_in[2];
        W_ih    = (const float*)d_in[3];
        W_hh    = (const float*)d_in[4];
        b_ih    = (const float*)d_in[5];
        b_hh    = (const float*)d_in[6];
        emb     = (const float*)d_in[7];
        W_out   = (const float*)d_in[8];
        b_out   = (const float*)d_in[9];
    }
    float* out = (float*)d_out;   // __output__ treated as float32 this round

    // priming: img_vec = relu(img @ W_feats^T + b); h = c = 0; first LSTM cell
    k_prime <<<dim3(8, 16),  256>>>(img, W_feats, b_feats);
    k_gates <<<dim3(32, 16), 256>>>(W_ih, W_hh, b_ih, b_hh);
    k_point <<<2048, 256>>>();

    // 15 greedy decode steps
    for (int t = 0; t < TSTEPS; t++) {
        k_embed  <<<1024, 128>>>(emb, t);
        k_gates  <<<dim3(32, 16), 256>>>(W_ih, W_hh, b_ih, b_hh);
        k_point  <<<2048, 256>>>();
        k_logits <<<dim3(188, 16), 256>>>(W_out, b_out);
        k_argmax <<<1024, 256>>>(out, t);
    }
}

// round 9
// speedup vs baseline: 1.4056x; 1.4056x over previous
#include <cuda_runtime.h>
#include <math.h>

#define BATCH   1024
#define EMBD    512
#define RNND    512
#define GATES   2048
#define VOCABO  11998
#define VPAD    12032      // 94 * 128
#define FEATSD  4096
#define TSTEPS  15

typedef unsigned long long u64;

// ---------------- scratch (__device__ globals; no runtime allocation) ----------
__device__ float g_x[BATCH * EMBD];
__device__ float g_h[BATCH * RNND];
__device__ float g_c[BATCH * RNND];
__device__ float g_gates[BATCH * GATES];
__device__ float g_logits[BATCH * VPAD];
__device__ int   g_words[BATCH];

// ---------------- packed f32x2 helpers -----------------------------------------
__device__ __forceinline__ u64 pack2(float lo, float hi) {
    u64 r; asm("mov.b64 %0, {%1, %2};" : "=l"(r) : "f"(lo), "f"(hi)); return r;
}
__device__ __forceinline__ void unpack2(u64 v, float& lo, float& hi) {
    asm("mov.b64 {%0, %1}, %2;" : "=f"(lo), "=f"(hi) : "l"(v));
}
__device__ __forceinline__ void ffma2(u64& d, u64 a, u64 b) {
    asm("fma.rn.f32x2 %0, %1, %2, %0;" : "+l"(d) : "l"(a), "l"(b));
}

// ---------------- activations (expf-only; robust under fast-math) --------------
__device__ __forceinline__ float sigm_f(float x) {
    return 1.0f / (1.0f + expf(-x));
}
__device__ __forceinline__ float tanh_f(float x) {
    float e = expf(-2.0f * fabsf(x));
    float t = (1.0f - e) / (1.0f + e);
    return copysignf(t, x);
}

// ================================================================================
// Kernel 1: g_x = relu(img[1024,4096] @ W_feats^T + b); zero h, c.  (proven R7)
// 64x64 tile, BK=32, 256 threads, 4x4/thread. grid(8,16).
// ================================================================================
__global__ __launch_bounds__(256) void k_prime(const float* __restrict__ A,
                                               const float* __restrict__ Bw,
                                               const float* __restrict__ bias) {
    __shared__ float As[32][68];
    __shared__ float Bs[32][68];
    const int tid = threadIdx.x;
    const int bm = blockIdx.y * 64, bn = blockIdx.x * 64;
    const int lr = tid >> 3, lk = (tid & 7) << 2;
    const int m0 = (tid >> 4) << 2, n0 = (tid & 15) << 2;
    float acc[4][4] = {};

    for (int s = 0; s < FEATSD / 32; s++) {
        const int ka = s * 32 + lk;
        float4 a0 = *(const float4*)&A [(size_t)(bm + lr)      * FEATSD + ka];
        float4 a1 = *(const float4*)&A [(size_t)(bm + lr + 32) * FEATSD + ka];
        float4 b0 = *(const float4*)&Bw[(size_t)(bn + lr)      * FEATSD + ka];
        float4 b1 = *(const float4*)&Bw[(size_t)(bn + lr + 32) * FEATSD + ka];
        __syncthreads();
        As[lk+0][lr] = a0.x; As[lk+1][lr] = a0.y; As[lk+2][lr] = a0.z; As[lk+3][lr] = a0.w;
        As[lk+0][lr+32] = a1.x; As[lk+1][lr+32] = a1.y; As[lk+2][lr+32] = a1.z; As[lk+3][lr+32] = a1.w;
        Bs[lk+0][lr] = b0.x; Bs[lk+1][lr] = b0.y; Bs[lk+2][lr] = b0.z; Bs[lk+3][lr] = b0.w;
        Bs[lk+0][lr+32] = b1.x; Bs[lk+1][lr+32] = b1.y; Bs[lk+2][lr+32] = b1.z; Bs[lk+3][lr+32] = b1.w;
        __syncthreads();
        #pragma unroll
        for (int kk = 0; kk < 32; kk++) {
            float4 a = *(const float4*)&As[kk][m0];
            float4 b = *(const float4*)&Bs[kk][n0];
            acc[0][0] += a.x*b.x; acc[0][1] += a.x*b.y; acc[0][2] += a.x*b.z; acc[0][3] += a.x*b.w;
            acc[1][0] += a.y*b.x; acc[1][1] += a.y*b.y; acc[1][2] += a.y*b.z; acc[1][3] += a.y*b.w;
            acc[2][0] += a.z*b.x; acc[2][1] += a.z*b.y; acc[2][2] += a.z*b.z; acc[2][3] += a.z*b.w;
            acc[3][0] += a.w*b.x; acc[3][1] += a.w*b.y; acc[3][2] += a.w*b.z; acc[3][3] += a.w*b.w;
        }
    }

    #pragma unroll
    for (int i = 0; i < 4; i++) {
        int m = bm + m0 + i;
        #pragma unroll
        for (int j = 0; j < 4; j++) {
            int n = bn + n0 + j;
            float v = fmaxf(acc[i][j] + bias[n], 0.0f);
            int idx = m * EMBD + n;
            g_x[idx] = v;
            g_h[idx] = 0.0f;
            g_c[idx] = 0.0f;
        }
    }
}

// ================================================================================
// Kernel 2: LSTM gates GEMM, f32x2 packed.
// g_gates[1024,2048] = [g_x | g_h] @ [W_ih | W_hh]^T + b_ih + b_hh
// 128x128 tile, BK=32, 256 thr, 8x8/thread (rows m0..m0+3, m0+64..m0+67;
// cols n0..n0+3, n0+64..n0+67 as 4 packed pairs). grid(16,8).
// ================================================================================
__global__ __launch_bounds__(256) void k_gates(const float* __restrict__ Wih,
                                               const float* __restrict__ Whh,
                                               const float* __restrict__ bih,
                                               const float* __restrict__ bhh) {
    __shared__ __align__(16) float As[32][132];
    __shared__ __align__(16) float Bs[32][132];
    const int tid = threadIdx.x;
    const int bm = blockIdx.y * 128, bn = blockIdx.x * 128;
    const int lr = tid >> 3;              // 0..31
    const int lk = (tid & 7) << 2;        // 0..28
    const int m0 = (tid >> 4) << 2;       // 0..60
    const int n0 = (tid & 15) << 2;       // 0..60
    u64 acc2[8][4] = {};

    for (int s = 0; s < 32; s++) {        // virtual K = 1024
        const int sk = s * 32;
        const float* Ap = (sk < 512) ? g_x : g_h;
        const float* Bp = (sk < 512) ? Wih : Whh;
        const int ka = (sk & 511) + lk;
        float4 ga[4], gb[4];
        #pragma unroll
        for (int u = 0; u < 4; u++) {
            ga[u] = *(const float4*)&Ap[(size_t)(bm + lr + 32*u) * 512 + ka];
            gb[u] = *(const float4*)&Bp[(size_t)(bn + lr + 32*u) * 512 + ka];
        }
        __syncthreads();
        #pragma unroll
        for (int u = 0; u < 4; u++) {
            int rr = lr + 32*u;
            As[lk+0][rr] = ga[u].x; As[lk+1][rr] = ga[u].y;
            As[lk+2][rr] = ga[u].z; As[lk+3][rr] = ga[u].w;
            Bs[lk+0][rr] = gb[u].x; Bs[lk+1][rr] = gb[u].y;
            Bs[lk+2][rr] = gb[u].z; Bs[lk+3][rr] = gb[u].w;
        }
        __syncthreads();
        #pragma unroll
        for (int kk = 0; kk < 32; kk++) {
            float4 a0 = *(const float4*)&As[kk][m0];
            float4 a1 = *(const float4*)&As[kk][m0 + 64];
            ulonglong2 b0 = *(const ulonglong2*)&Bs[kk][n0];
            ulonglong2 b1 = *(const ulonglong2*)&Bs[kk][n0 + 64];
            u64 av[8];
            av[0] = pack2(a0.x, a0.x); av[1] = pack2(a0.y, a0.y);
            av[2] = pack2(a0.z, a0.z); av[3] = pack2(a0.w, a0.w);
            av[4] = pack2(a1.x, a1.x); av[5] = pack2(a1.y, a1.y);
            av[6] = pack2(a1.z, a1.z); av[7] = pack2(a1.w, a1.w);
            u64 bv[4] = { b0.x, b0.y, b1.x, b1.y };
            #pragma unroll
            for (int i = 0; i < 8; i++)
                #pragma unroll
                for (int j = 0; j < 4; j++)
                    ffma2(acc2[i][j], av[i], bv[j]);
        }
    }

    #pragma unroll
    for (int i = 0; i < 8; i++) {
        int m = bm + m0 + ((i < 4) ? i : 60 + i);            // i=4 -> +64
        #pragma unroll
        for (int j = 0; j < 4; j++) {
            int n = bn + n0 + ((j < 2) ? 2*j : 60 + 2*j);    // j=2 -> +64
            float lo, hi; unpack2(acc2[i][j], lo, hi);
            g_gates[m * GATES + n]     = lo + bih[n]     + bhh[n];
            g_gates[m * GATES + n + 1] = hi + bih[n + 1] + bhh[n + 1];
        }
    }
}

// ================================================================================
// Kernel 3: logits GEMM, f32x2 packed. g_logits = g_h @ W_out^T + b_out.
// Same scheme, K=512. grid(94,8). OOB vocab rows loaded as zero / not stored.
// ================================================================================
__global__ __launch_bounds__(256) void k_logits(const float* __restrict__ Wout,
                                                const float* __restrict__ bout) {
    __shared__ __align__(16) float As[32][132];
    __shared__ __align__(16) float Bs[32][132];
    const int tid = threadIdx.x;
    const int bm = blockIdx.y * 128, bn = blockIdx.x * 128;
    const int lr = tid >> 3;
    const int lk = (tid & 7) << 2;
    const int m0 = (tid >> 4) << 2;
    const int n0 = (tid & 15) << 2;
    u64 acc2[8][4] = {};
    const float4 z4 = make_float4(0.f, 0.f, 0.f, 0.f);

    for (int s = 0; s < 16; s++) {        // K = 512
        const int ka = s * 32 + lk;
        float4 ga[4], gb[4];
        #pragma unroll
        for (int u = 0; u < 4; u++) {
            ga[u] = *(const float4*)&g_h[(size_t)(bm + lr + 32*u) * 512 + ka];
            int br = bn + lr + 32*u;
            gb[u] = (br < VOCABO) ? *(const float4*)&Wout[(size_t)br * 512 + ka] : z4;
        }
        __syncthreads();
        #pragma unroll
        for (int u = 0; u < 4; u++) {
            int rr = lr + 32*u;
            As[lk+0][rr] = ga[u].x; As[lk+1][rr] = ga[u].y;
            As[lk+2][rr] = ga[u].z; As[lk+3][rr] = ga[u].w;
            Bs[lk+0][rr] = gb[u].x; Bs[lk+1][rr] = gb[u].y;
            Bs[lk+2][rr] = gb[u].z; Bs[lk+3][rr] = gb[u].w;
        }
        __syncthreads();
        #pragma unroll
        for (int kk = 0; kk < 32; kk++) {
            float4 a0 = *(const float4*)&As[kk][m0];
            float4 a1 = *(const float4*)&As[kk][m0 + 64];
            ulonglong2 b0 = *(const ulonglong2*)&Bs[kk][n0];
            ulonglong2 b1 = *(const ulonglong2*)&Bs[kk][n0 + 64];
            u64 av[8];
            av[0] = pack2(a0.x, a0.x); av[1] = pack2(a0.y, a0.y);
            av[2] = pack2(a0.z, a0.z); av[3] = pack2(a0.w, a0.w);
            av[4] = pack2(a1.x, a1.x); av[5] = pack2(a1.y, a1.y);
            av[6] = pack2(a1.z, a1.z); av[7] = pack2(a1.w, a1.w);
            u64 bv[4] = { b0.x, b0.y, b1.x, b1.y };
            #pragma unroll
            for (int i = 0; i < 8; i++)
                #pragma unroll
                for (int j = 0; j < 4; j++)
                    ffma2(acc2[i][j], av[i], bv[j]);
        }
    }

    #pragma unroll
    for (int i = 0; i < 8; i++) {
        int m = bm + m0 + ((i < 4) ? i : 60 + i);
        #pragma unroll
        for (int j = 0; j < 4; j++) {
            int n = bn + n0 + ((j < 2) ? 2*j : 60 + 2*j);
            float lo, hi; unpack2(acc2[i][j], lo, hi);
            if (n < VOCABO)     g_logits[m * VPAD + n]     = lo + bout[n];
            if (n + 1 < VOCABO) g_logits[m * VPAD + n + 1] = hi + bout[n + 1];
        }
    }
}

// -------- Kernel 4: LSTM pointwise (i, f, g, o torch order) ---------------------
__global__ void k_point() {
    int idx = blockIdx.x * blockDim.x + threadIdx.x;
    int b = idx >> 9, n = idx & 511;
    const float* g = g_gates + b * GATES;
    float ig = sigm_f(g[n]);
    float fg = sigm_f(g[512 + n]);
    float gg = tanh_f(g[1024 + n]);
    float og = sigm_f(g[1536 + n]);
    float c = fg * g_c[idx] + ig * gg;
    g_c[idx] = c;
    g_h[idx] = og * tanh_f(c);
}

// -------- Kernel 5: embedding gather -------------------------------------------
__global__ void k_embed(const float* __restrict__ emb, int t) {
    int b = blockIdx.x;
    int w = (t == 0) ? 1 : g_words[b];
    const float4* src = (const float4*)(emb + (size_t)w * EMBD);
    float4* dst = (float4*)(g_x + (size_t)b * EMBD);
    dst[threadIdx.x] = src[threadIdx.x];
}

// -------- Kernel 6: per-row argmax; output as float32 ---------------------------
__global__ __launch_bounds__(256) void k_argmax(float* __restrict__ out, int t) {
    __shared__ float sv[256];
    __shared__ int   si[256];
    const int b = blockIdx.x;
    const int tid = threadIdx.x;
    const float* row = g_logits + (size_t)b * VPAD;

    float bv = -1e30f;
    int bi = 0;
    for (int n = tid; n < VOCABO; n += 256) {
        float v = row[n];
        if (v > bv) { bv = v; bi = n; }
    }
    sv[tid] = bv; si[tid] = bi;
    __syncthreads();
    for (int s = 128; s > 0; s >>= 1) {
        if (tid < s) {
            float ov = sv[tid + s]; int oi = si[tid + s];
            if (ov > sv[tid] || (ov == sv[tid] && oi < si[tid])) {
                sv[tid] = ov; si[tid] = oi;
            }
        }
        __syncthreads();
    }
    if (tid == 0) {
        out[b * TSTEPS + t] = (float)si[0];
        g_words[b] = si[0] + 2;
    }
}

// ================================================================================
extern "C" void kernel_launch(void* const* d_in, const int* in_sizes, int n_in,
                              void* d_out, int out_size) {
    const float *img = 0, *W_feats = 0, *b_feats = 0, *W_ih = 0, *W_hh = 0,
                *b_ih = 0, *b_hh = 0, *emb = 0, *W_out = 0, *b_out = 0;
    for (int i = 0; i < n_in; i++) {
        const float* p = (const float*)d_in[i];
        switch (in_sizes[i]) {
            case 4194304: img = p; break;
            case 2097152: W_feats = p; break;
            case 512:     b_feats = p; break;
            case 1048576: if (!W_ih) W_ih = p; else W_hh = p; break;
            case 2048:    if (!b_ih) b_ih = p; else b_hh = p; break;
            case 6144000: emb = p; break;
            case 6142976: W_out = p; break;
            case 11998:   b_out = p; break;
            default: break;
        }
    }
    if (!img || !W_feats || !b_feats || !W_ih || !W_hh || !b_ih || !b_hh ||
        !emb || !W_out || !b_out) {
        img     = (const float*)d_in[0];
        W_feats = (const float*)d_in[1];
        b_feats = (const float*)d_in[2];
        W_ih    = (const float*)d_in[3];
        W_hh    = (const float*)d_in[4];
        b_ih    = (const float*)d_in[5];
        b_hh    = (const float*)d_in[6];
        emb     = (const float*)d_in[7];
        W_out   = (const float*)d_in[8];
        b_out   = (const float*)d_in[9];
    }
    float* out = (float*)d_out;

    k_prime <<<dim3(8, 16),  256>>>(img, W_feats, b_feats);
    k_gates <<<dim3(16, 8),  256>>>(W_ih, W_hh, b_ih, b_hh);
    k_point <<<2048, 256>>>();

    for (int t = 0; t < TSTEPS; t++) {
        k_embed  <<<1024, 128>>>(emb, t);
        k_gates  <<<dim3(16, 8), 256>>>(W_ih, W_hh, b_ih, b_hh);
        k_point  <<<2048, 256>>>();
        k_logits <<<dim3(94, 8), 256>>>(W_out, b_out);
        k_argmax <<<1024, 256>>>(out, t);
    }
}